// round 12
// baseline (speedup 1.0000x reference)
#include <cuda_runtime.h>
#include <cstdint>
#include <math.h>

// BaseSmear: project 64^3 grid points into 8 camera images, nearest-neighbor
// gather of 32 feature channels + depth + validity + ray direction.
//
//   Pipelined: per-image transpose (stream A) overlapped with per-image
//   smear (stream B) via event edges -> one bandwidth-saturated phase
//   instead of transpose-then-smear.
//
//   smear: per-thread projection; cooperative gather (8 lanes share one
//   pixel's 128B channel vector, offsets via SHFL) with all 8 LDG.128
//   hoisted (MLP=8); extras stored inside the latency window; warp-local
//   swizzled smem stage; STG.128 + __stcs streaming output.

#define II 8
#define CC 32
#define HH 240
#define WW 320
#define HW (HH*WW)          // 76800
#define NN (64*64*64)       // 262144
#define NN4 (NN/4)          // 65536

__device__ float g_imgT[(size_t)II * HW * CC];   // 78.6 MB channels-last scratch

// ---- transpose one image: [C, HW] -> [HW, C] --------------------------------
__global__ __launch_bounds__(256) void transpose_kernel(const float* __restrict__ images,
                                                        int img) {
    __shared__ float tile[32][33];
    const int pixbase = blockIdx.x * 32;
    const int lane = threadIdx.x & 31;
    const int wy   = threadIdx.x >> 5;               // 0..7

    const float* src = images + (size_t)img * CC * HW + pixbase;
    #pragma unroll
    for (int r = 0; r < 4; r++) {
        const int c = wy + r * 8;
        tile[c][lane] = src[(size_t)c * HW + lane];
    }
    __syncthreads();
    float* dst = g_imgT + ((size_t)img * HW + pixbase) * CC;
    #pragma unroll
    for (int r = 0; r < 4; r++) {
        const int p = wy + r * 8;
        dst[(size_t)p * CC + lane] = tile[lane][p];
    }
}

// ---- smear one image: project + MLP-8 coop gather + stage + STG.128 ---------
__global__ __launch_bounds__(256, 4) void smear_kernel(
    const float* __restrict__ trans,    // [8,3,4]
    const float* __restrict__ Tcw,      // [8,4,4]
    const float* __restrict__ coords,   // [3,64,64,64]
    float* __restrict__ out,            // [8,37,N] then [3,N]
    int i)
{
    __shared__ float s[8][32 * 32];     // 4 KB per warp

    const int tid  = threadIdx.x;
    const int lane = tid & 31;
    const int wrp  = tid >> 5;
    const int nb   = blockIdx.x << 8;        // block's base point
    const int n    = nb + tid;

    // ---------- Phase A: per-thread projection ----------
    const float px = coords[n];
    const float py = coords[NN + n];
    const float pz = coords[2 * NN + n];

    const float* T = Tcw   + i * 16;
    const float* P = trans + i * 12;

    const float depth = T[8] * px + T[9] * py + T[10] * pz + T[11];
    const float w  = P[8] * px + P[9] * py + P[10] * pz + P[11];
    const float ws = (fabsf(w) < 1e-8f) ? 1e-8f : w;
    const float u  = (P[0] * px + P[1] * py + P[2] * pz + P[3]) / ws;
    const float v  = (P[4] * px + P[5] * py + P[6] * pz + P[7]) / ws;

    const bool valid = (u >= 0.0f) && (u <= (float)(WW - 1)) &&
                       (v >= 0.0f) && (v <= (float)(HH - 1)) &&
                       (depth > 0.0f);
    const float validf = valid ? 1.0f : 0.0f;

    const int ui = (int)fminf(fmaxf(rintf(u), 0.0f), (float)(WW - 1));
    const int vi = (int)fminf(fmaxf(rintf(v), 0.0f), (float)(HH - 1));
    const int poffEnc = valid ? (vi * WW + ui) : -1;

    // ---------- Phase B1: hoisted cooperative gather (MLP = 8) ----------
    const int chunk = lane & 7;              // which 16B of the 128B pixel vec
    const int ptoff = lane >> 3;             // which of 4 points this instr

    const float* imgBase = g_imgT + (size_t)i * HW * CC + chunk * 4;
    const float4 z4 = make_float4(0.f, 0.f, 0.f, 0.f);

    float4 f[8];
    #pragma unroll
    for (int it = 0; it < 8; it++) {
        const int pe = __shfl_sync(0xffffffffu, poffEnc, it * 4 + ptoff);
        f[it] = z4;
        if (pe >= 0)
            f[it] = __ldg((const float4*)(imgBase + (size_t)pe * CC));
    }

    // ---------- Phase A2: extras + coords (fills the gather latency) --------
    {
        const float ccx = -(T[0] * T[3] + T[4] * T[7] + T[8]  * T[11]);
        const float ccy = -(T[1] * T[3] + T[5] * T[7] + T[9]  * T[11]);
        const float ccz = -(T[2] * T[3] + T[6] * T[7] + T[10] * T[11]);
        float dx = px - ccx, dy = py - ccy, dz = pz - ccz;
        const float inv = 1.0f / (sqrtf(dx * dx + dy * dy + dz * dz) + 1e-8f);

        float* eo = out + (size_t)i * 37 * NN + n;
        __stcs(eo + (size_t)32 * NN, depth);
        __stcs(eo + (size_t)33 * NN, validf);
        __stcs(eo + (size_t)34 * NN, dx * inv);
        __stcs(eo + (size_t)35 * NN, dy * inv);
        __stcs(eo + (size_t)36 * NN, dz * inv);
        if (i == 0) {
            float* tail = out + (size_t)II * 37 * NN;
            __stcs(tail + n,          px);
            __stcs(tail + NN + n,     py);
            __stcs(tail + 2 * NN + n, pz);
        }
    }

    // ---------- Phase B2: drain gathers into warp-local swizzled smem -------
    const int ch = chunk * 4;
    float* sw = s[wrp];
    #pragma unroll
    for (int it = 0; it < 8; it++) {
        const int q = it * 4 + ptoff;        // point index within warp (0..31)
        const int base = ch * 32 + (q ^ (chunk * 4));
        sw[base]      = f[it].x;
        sw[base + 32] = f[it].y;
        sw[base + 64] = f[it].z;
        sw[base + 96] = f[it].w;
    }

    __syncwarp();

    // ---------- Phase C: warp-local coalesced float4 streamed output ----------
    float4* o4 = (float4*)out + (size_t)i * 37 * NN4 + (nb >> 2) + wrp * 8;
    #pragma unroll
    for (int r = 0; r < 8; r++) {
        const int c  = r * 4 + (lane >> 3);  // channel 0..31
        const int qq = lane & 7;             // float4 index within warp (0..7)
        const float4 val = *(const float4*)&sw[c * 32 + ((qq * 4) ^ (c & 28))];
        __stcs(&o4[(size_t)c * NN4 + qq], val);
    }
}

extern "C" void kernel_launch(void* const* d_in, const int* in_sizes, int n_in,
                              void* d_out, int out_size) {
    const float* images = (const float*)d_in[0];
    const float* trans  = (const float*)d_in[1];
    const float* Tcw    = (const float*)d_in[2];
    const float* coords = (const float*)d_in[3];
    float* out = (float*)d_out;

    // lazily created host-side objects (no device memory involved)
    static cudaStream_t sA = nullptr, sB = nullptr;
    static cudaEvent_t evRoot, evA, evB, evT[II];
    if (!sA) {
        cudaStreamCreateWithFlags(&sA, cudaStreamNonBlocking);
        cudaStreamCreateWithFlags(&sB, cudaStreamNonBlocking);
        cudaEventCreateWithFlags(&evRoot, cudaEventDisableTiming);
        cudaEventCreateWithFlags(&evA,    cudaEventDisableTiming);
        cudaEventCreateWithFlags(&evB,    cudaEventDisableTiming);
        for (int i = 0; i < II; i++)
            cudaEventCreateWithFlags(&evT[i], cudaEventDisableTiming);
    }

    // fork both worker streams from the launch stream
    cudaEventRecord(evRoot, 0);
    cudaStreamWaitEvent(sA, evRoot, 0);
    cudaStreamWaitEvent(sB, evRoot, 0);

    // pipelined per-image: transpose(i) on A -> smear(i) on B
    for (int i = 0; i < II; i++) {
        transpose_kernel<<<HW / 32, 256, 0, sA>>>(images, i);
        cudaEventRecord(evT[i], sA);
        cudaStreamWaitEvent(sB, evT[i], 0);
        smear_kernel<<<NN / 256, 256, 0, sB>>>(trans, Tcw, coords, out, i);
    }

    // join back into the launch stream
    cudaEventRecord(evA, sA);
    cudaEventRecord(evB, sB);
    cudaStreamWaitEvent(0, evA, 0);
    cudaStreamWaitEvent(0, evB, 0);
}